// round 11
// baseline (speedup 1.0000x reference)
#include <cuda_runtime.h>
#include <math.h>

#define cN1 262144
#define cN2 65536
#define cN3 16384
#define cE1 524288
#define cE2 262144
#define NEG_SLOPE 0.2f
#define BCAP 64

// ---------------- static device scratch ----------------
__device__ float g_V1s[128 * 4];
__device__ float g_V1d[128 * 4];
__device__ float g_v2s[256];
__device__ float g_v2d[256];
__device__ float g_bns[256];
__device__ float g_bnb[256];
__device__ float g_as1[cN1 * 4];
__device__ float g_ad1[cN2 * 4];
__device__ float g_as2[cN2];
__device__ float g_ad2[cN3];
__device__ int   g_cnt1[cN2];
__device__ int   g_cnt2[cN3];
__device__ int   g_bkt1[(size_t)cN2 * BCAP];
__device__ int   g_bkt2[(size_t)cN3 * BCAP];
__device__ float g_xagg1[(size_t)cN2 * 512];
__device__ float g_h1[(size_t)cN2 * 256];
__device__ float g_xagg2[(size_t)cN3 * 256];

// f32x2 packed-math helpers (sm_103a FFMA2 path)
#define FMA2(acc, a, b) asm("fma.rn.f32x2 %0, %1, %2, %0;" : "+l"(acc) : "l"(a), "l"(b))
#define PACK2(out, x)   asm("mov.b64 %0, {%1, %1};" : "=l"(out) : "f"(x))
#define UNPACK2(lo, hi, v) asm("mov.b64 {%0, %1}, %2;" : "=f"(lo), "=f"(hi) : "l"(v))
#define LDS_V2U64(a0, a1, addr) \
    asm("ld.shared.v2.u64 {%0, %1}, [%2];" : "=l"(a0), "=l"(a1) : "r"(addr))

// ---------------- prep: projections + BN consts + zero bucket counters ----------------
__global__ void k_prep_zero(const float* __restrict__ W1s, const float* __restrict__ W1d,
                            const float* __restrict__ a1s, const float* __restrict__ a1d,
                            const float* __restrict__ b1, const float* __restrict__ gamma,
                            const float* __restrict__ beta, const float* __restrict__ rmean,
                            const float* __restrict__ rvar,
                            const float* __restrict__ W2s, const float* __restrict__ W2d,
                            const float* __restrict__ a2s, const float* __restrict__ a2d) {
    int gi = blockIdx.x * 512 + threadIdx.x;
    if (gi < cN2) g_cnt1[gi] = 0;
    if (gi < cN3) g_cnt2[gi] = 0;
    if (blockIdx.x == 0) {
        int t = threadIdx.x;
        {
            int i = t >> 2, h = t & 3;
            float ss = 0.f, sd = 0.f;
            for (int c = 0; c < 64; c++) {
                ss += W1s[i * 256 + h * 64 + c] * a1s[h * 64 + c];
                sd += W1d[i * 256 + h * 64 + c] * a1d[h * 64 + c];
            }
            g_V1s[i * 4 + h] = ss;
            g_V1d[i * 4 + h] = sd;
        }
        if (t < 256) {
            float ss = 0.f, sd = 0.f;
            for (int d = 0; d < 64; d++) {
                ss += W2s[t * 64 + d] * a2s[d];
                sd += W2d[t * 64 + d] * a2d[d];
            }
            g_v2s[t] = ss;
            g_v2d[t] = sd;
            float sc = gamma[t] * rsqrtf(rvar[t] + 1e-5f);
            g_bns[t] = sc;
            g_bnb[t] = beta[t] + (b1[t] - rmean[t]) * sc;
        }
    }
}

// ---------------- no-op (aligns ncu capture slot onto k_mega) ----------------
__global__ void k_noop() {}

// ---------------- mega: layer-1 logit GEMVs (warp/node) + both bucket scatters ----------------
#define A1_BLOCKS (cN1 / 8)
#define SC1_BLOCKS (cE1 / 256)
#define SC2_BLOCKS (cE2 / 256)
__global__ void k_mega(const float* __restrict__ x,
                       const int* __restrict__ src1, const int* __restrict__ dst1,
                       const int* __restrict__ src2, const int* __restrict__ dst2) {
    int b = blockIdx.x;
    if (b < SC1_BLOCKS) {
        int e = b * 256 + threadIdx.x;
        int d = dst1[e];
        int p = atomicAdd(&g_cnt1[d], 1);
        g_bkt1[(size_t)d * BCAP + (p < BCAP ? p : BCAP - 1)] = src1[e];
        return;
    }
    if (b < SC1_BLOCKS + SC2_BLOCKS) {
        int e = (b - SC1_BLOCKS) * 256 + threadIdx.x;
        int d = dst2[e];
        int p = atomicAdd(&g_cnt2[d], 1);
        g_bkt2[(size_t)d * BCAP + (p < BCAP ? p : BCAP - 1)] = src2[e];
        return;
    }
    int w = ((b - SC1_BLOCKS - SC2_BLOCKS) * 256 + threadIdx.x) >> 5;
    int lane = threadIdx.x & 31;
    if (w >= cN1) return;
    float4 xv = *(const float4*)(x + (size_t)w * 128 + lane * 4);
    float ps0 = 0, ps1 = 0, ps2 = 0, ps3 = 0;
    float pd0 = 0, pd1 = 0, pd2 = 0, pd3 = 0;
    bool isd = (w < cN2);
    const float xj[4] = {xv.x, xv.y, xv.z, xv.w};
#pragma unroll
    for (int j = 0; j < 4; j++) {
        int i = lane * 4 + j;
        float v = xj[j];
        ps0 += v * g_V1s[i * 4 + 0];
        ps1 += v * g_V1s[i * 4 + 1];
        ps2 += v * g_V1s[i * 4 + 2];
        ps3 += v * g_V1s[i * 4 + 3];
        if (isd) {
            pd0 += v * g_V1d[i * 4 + 0];
            pd1 += v * g_V1d[i * 4 + 1];
            pd2 += v * g_V1d[i * 4 + 2];
            pd3 += v * g_V1d[i * 4 + 3];
        }
    }
#pragma unroll
    for (int o = 16; o; o >>= 1) {
        ps0 += __shfl_down_sync(0xffffffffu, ps0, o);
        ps1 += __shfl_down_sync(0xffffffffu, ps1, o);
        ps2 += __shfl_down_sync(0xffffffffu, ps2, o);
        ps3 += __shfl_down_sync(0xffffffffu, ps3, o);
        if (isd) {
            pd0 += __shfl_down_sync(0xffffffffu, pd0, o);
            pd1 += __shfl_down_sync(0xffffffffu, pd1, o);
            pd2 += __shfl_down_sync(0xffffffffu, pd2, o);
            pd3 += __shfl_down_sync(0xffffffffu, pd3, o);
        }
    }
    if (lane == 0) {
        g_as1[w * 4 + 0] = ps0;
        g_as1[w * 4 + 1] = ps1;
        g_as1[w * 4 + 2] = ps2;
        g_as1[w * 4 + 3] = ps3;
        if (isd) {
            g_ad1[w * 4 + 0] = pd0;
            g_ad1[w * 4 + 1] = pd1;
            g_ad1[w * 4 + 2] = pd2;
            g_ad1[w * 4 + 3] = pd3;
        }
    }
}

// ---------------- layer-1 aggregation: TWO warps per dst (column split) ----------------
__global__ void k_agg1(const float* __restrict__ x) {
    int gw = (blockIdx.x * blockDim.x + threadIdx.x) >> 5;
    int lane = threadIdx.x & 31;
    int w = gw >> 1, half = gw & 1;
    if (w >= cN2) return;
    int cnt = g_cnt1[w];
    int end = cnt < BCAP ? cnt : BCAP;
    const int* bkt = g_bkt1 + (size_t)w * BCAP;
    float4 ad = *(const float4*)(g_ad1 + w * 4);
    int coff = half * 64 + lane * 2;
    float a00 = 0.f, a01 = 0.f, a10 = 0.f, a11 = 0.f;
    float a20 = 0.f, a21 = 0.f, a30 = 0.f, a31 = 0.f;
    float s0 = 0.f, s1 = 0.f, s2 = 0.f, s3 = 0.f;
#pragma unroll 4
    for (int e = 0; e < end; e++) {
        int s = bkt[e];
        float4 av = *(const float4*)(g_as1 + s * 4);
        float2 xv = *(const float2*)(x + (size_t)s * 128 + coff);
        float v0 = av.x + ad.x; v0 = v0 > 0.f ? v0 : NEG_SLOPE * v0;
        float v1 = av.y + ad.y; v1 = v1 > 0.f ? v1 : NEG_SLOPE * v1;
        float v2 = av.z + ad.z; v2 = v2 > 0.f ? v2 : NEG_SLOPE * v2;
        float v3 = av.w + ad.w; v3 = v3 > 0.f ? v3 : NEG_SLOPE * v3;
        float w0 = __expf(v0), w1 = __expf(v1);
        float w2 = __expf(v2), w3 = __expf(v3);
        s0 += w0; s1 += w1; s2 += w2; s3 += w3;
        a00 += w0 * xv.x; a01 += w0 * xv.y;
        a10 += w1 * xv.x; a11 += w1 * xv.y;
        a20 += w2 * xv.x; a21 += w2 * xv.y;
        a30 += w3 * xv.x; a31 += w3 * xv.y;
    }
    float r0 = 1.f / fmaxf(s0, 1e-16f);
    float r1 = 1.f / fmaxf(s1, 1e-16f);
    float r2 = 1.f / fmaxf(s2, 1e-16f);
    float r3 = 1.f / fmaxf(s3, 1e-16f);
    float* o = g_xagg1 + (size_t)w * 512 + coff;
    float2 t;
    t.x = a00 * r0; t.y = a01 * r0; *(float2*)(o + 0)   = t;
    t.x = a10 * r1; t.y = a11 * r1; *(float2*)(o + 128) = t;
    t.x = a20 * r2; t.y = a21 * r2; *(float2*)(o + 256) = t;
    t.x = a30 * r3; t.y = a31 * r3; *(float2*)(o + 384) = t;
}

// ---------------- layer-1 GEMM (R5 config: 256 thr, 8x4/thread, 2 k-chunks) ----------------
__global__ void k_gemm1(const float* __restrict__ W1s) {
    __shared__ float As[64 * 128];   // [k][r] transposed
    __shared__ float Bs[64 * 64];    // [k][c]
    int d0 = blockIdx.x * 128;
    int hh = blockIdx.y;
    int tid = threadIdx.x;
    int r0 = (tid >> 4) * 8, c0 = (tid & 15) * 4;
    unsigned long long acc[4][4];
#pragma unroll
    for (int p = 0; p < 4; p++)
#pragma unroll
        for (int c = 0; c < 4; c++) acc[p][c] = 0ull;
    unsigned sA = (unsigned)__cvta_generic_to_shared(As + r0);
#pragma unroll
    for (int kb = 0; kb < 2; kb++) {
        if (kb) __syncthreads();
#pragma unroll
        for (int i = 0; i < 8; i++) {
            int idx = i * 256 + tid;
            int r = idx & 127;
            int k0 = (idx >> 7) * 4;
            float4 v = *(const float4*)(g_xagg1 + (size_t)(d0 + r) * 512 + hh * 128 + kb * 64 + k0);
            As[(k0 + 0) * 128 + r] = v.x;
            As[(k0 + 1) * 128 + r] = v.y;
            As[(k0 + 2) * 128 + r] = v.z;
            As[(k0 + 3) * 128 + r] = v.w;
        }
#pragma unroll
        for (int i = 0; i < 4; i++) {
            int idx = i * 256 + tid;
            int k = idx >> 4, c = (idx & 15) * 4;
            *(float4*)(Bs + k * 64 + c) = *(const float4*)(W1s + (kb * 64 + k) * 256 + hh * 64 + c);
        }
        __syncthreads();
#pragma unroll 8
        for (int kk = 0; kk < 64; kk++) {
            unsigned long long a01, a23, a45, a67;
            LDS_V2U64(a01, a23, sA + kk * 512);
            LDS_V2U64(a45, a67, sA + kk * 512 + 16);
            float4 b = *(float4*)(Bs + kk * 64 + c0);
            unsigned long long bx, by, bz, bw;
            PACK2(bx, b.x); PACK2(by, b.y); PACK2(bz, b.z); PACK2(bw, b.w);
            FMA2(acc[0][0], a01, bx); FMA2(acc[0][1], a01, by); FMA2(acc[0][2], a01, bz); FMA2(acc[0][3], a01, bw);
            FMA2(acc[1][0], a23, bx); FMA2(acc[1][1], a23, by); FMA2(acc[1][2], a23, bz); FMA2(acc[1][3], a23, bw);
            FMA2(acc[2][0], a45, bx); FMA2(acc[2][1], a45, by); FMA2(acc[2][2], a45, bz); FMA2(acc[2][3], a45, bw);
            FMA2(acc[3][0], a67, bx); FMA2(acc[3][1], a67, by); FMA2(acc[3][2], a67, bz); FMA2(acc[3][3], a67, bw);
        }
    }
    int colb = hh * 64 + c0;
    float4 sc = *(const float4*)(g_bns + colb);
    float4 sh = *(const float4*)(g_bnb + colb);
#pragma unroll
    for (int p = 0; p < 4; p++) {
        float lo[4], hi[4];
#pragma unroll
        for (int c = 0; c < 4; c++) UNPACK2(lo[c], hi[c], acc[p][c]);
        float e0, e1, e2, e3;
        e0 = lo[0] * sc.x + sh.x; e1 = lo[1] * sc.y + sh.y;
        e2 = lo[2] * sc.z + sh.z; e3 = lo[3] * sc.w + sh.w;
        e0 = e0 > 0.f ? e0 : (__expf(e0) - 1.f);
        e1 = e1 > 0.f ? e1 : (__expf(e1) - 1.f);
        e2 = e2 > 0.f ? e2 : (__expf(e2) - 1.f);
        e3 = e3 > 0.f ? e3 : (__expf(e3) - 1.f);
        float4 t = {e0, e1, e2, e3};
        *(float4*)(g_h1 + (size_t)(d0 + r0 + 2 * p) * 256 + colb) = t;
        e0 = hi[0] * sc.x + sh.x; e1 = hi[1] * sc.y + sh.y;
        e2 = hi[2] * sc.z + sh.z; e3 = hi[3] * sc.w + sh.w;
        e0 = e0 > 0.f ? e0 : (__expf(e0) - 1.f);
        e1 = e1 > 0.f ? e1 : (__expf(e1) - 1.f);
        e2 = e2 > 0.f ? e2 : (__expf(e2) - 1.f);
        e3 = e3 > 0.f ? e3 : (__expf(e3) - 1.f);
        float4 u = {e0, e1, e2, e3};
        *(float4*)(g_h1 + (size_t)(d0 + r0 + 2 * p + 1) * 256 + colb) = u;
    }
}

// ---------------- layer-2 logit GEMVs ----------------
__global__ void k_a2() {
    int w = (blockIdx.x * blockDim.x + threadIdx.x) >> 5;
    int lane = threadIdx.x & 31;
    if (w >= cN2) return;
    const float* row = g_h1 + (size_t)w * 256;
    float4 h0 = *(const float4*)(row + lane * 4);
    float4 h1v = *(const float4*)(row + 128 + lane * 4);
    float4 va = *(const float4*)(g_v2s + lane * 4);
    float4 vb = *(const float4*)(g_v2s + 128 + lane * 4);
    float s = h0.x * va.x + h0.y * va.y + h0.z * va.z + h0.w * va.w +
              h1v.x * vb.x + h1v.y * vb.y + h1v.z * vb.z + h1v.w * vb.w;
    float d = 0.f;
    bool isd = (w < cN3);
    if (isd) {
        float4 da = *(const float4*)(g_v2d + lane * 4);
        float4 db = *(const float4*)(g_v2d + 128 + lane * 4);
        d = h0.x * da.x + h0.y * da.y + h0.z * da.z + h0.w * da.w +
            h1v.x * db.x + h1v.y * db.y + h1v.z * db.z + h1v.w * db.w;
    }
#pragma unroll
    for (int o = 16; o; o >>= 1) {
        s += __shfl_down_sync(0xffffffffu, s, o);
        if (isd) d += __shfl_down_sync(0xffffffffu, d, o);
    }
    if (lane == 0) {
        g_as2[w] = s;
        if (isd) g_ad2[w] = d;
    }
}

// ---------------- layer-2 aggregation: TWO warps per dst (column split) ----------------
__global__ void k_agg2() {
    int gw = (blockIdx.x * blockDim.x + threadIdx.x) >> 5;
    int lane = threadIdx.x & 31;
    int w = gw >> 1, half = gw & 1;
    if (w >= cN3) return;
    int cnt = g_cnt2[w];
    int end = cnt < BCAP ? cnt : BCAP;
    const int* bkt = g_bkt2 + (size_t)w * BCAP;
    float ad = g_ad2[w];
    int coff = half * 128 + lane * 4;
    float a0 = 0.f, a1 = 0.f, a2 = 0.f, a3 = 0.f;
    float ss = 0.f;
#pragma unroll 4
    for (int e = 0; e < end; e++) {
        int s = bkt[e];
        float v = g_as2[s] + ad;
        v = v > 0.f ? v : NEG_SLOPE * v;
        float wt = __expf(v);
        ss += wt;
        float4 hv = *(const float4*)(g_h1 + (size_t)s * 256 + coff);
        a0 += wt * hv.x; a1 += wt * hv.y; a2 += wt * hv.z; a3 += wt * hv.w;
    }
    float r = 1.f / fmaxf(ss, 1e-16f);
    float4 t = {a0 * r, a1 * r, a2 * r, a3 * r};
    *(float4*)(g_xagg2 + (size_t)w * 256 + coff) = t;
}

// ---------------- layer-2 GEMM: 64x64 tile, K=256 in 4 chunks, 32KB smem ----------------
__global__ void k_gemm2(const float* __restrict__ W2s, const float* __restrict__ b2,
                        float* __restrict__ out) {
    __shared__ float As[64 * 64];   // [k][r]
    __shared__ float Bs[64 * 64];   // [k][c]
    int d0 = blockIdx.x * 64;
    int tid = threadIdx.x;
    int r0 = (tid >> 4) * 4, c0 = (tid & 15) * 4;
    unsigned long long acc[2][4];
#pragma unroll
    for (int p = 0; p < 2; p++)
#pragma unroll
        for (int c = 0; c < 4; c++) acc[p][c] = 0ull;
    unsigned sA = (unsigned)__cvta_generic_to_shared(As + r0);
#pragma unroll
    for (int kb = 0; kb < 4; kb++) {
        if (kb) __syncthreads();
#pragma unroll
        for (int i = 0; i < 4; i++) {
            int idx = i * 256 + tid;
            int r = idx & 63;
            int k0 = (idx >> 6) * 4;
            float4 v = *(const float4*)(g_xagg2 + (size_t)(d0 + r) * 256 + kb * 64 + k0);
            As[(k0 + 0) * 64 + r] = v.x;
            As[(k0 + 1) * 64 + r] = v.y;
            As[(k0 + 2) * 64 + r] = v.z;
            As[(k0 + 3) * 64 + r] = v.w;
        }
#pragma unroll
        for (int i = 0; i < 4; i++) {
            int idx = i * 256 + tid;
            int k = idx >> 4, c = (idx & 15) * 4;
            *(float4*)(Bs + k * 64 + c) = *(const float4*)(W2s + (kb * 64 + k) * 64 + c);
        }
        __syncthreads();
#pragma unroll 8
        for (int kk = 0; kk < 64; kk++) {
            unsigned long long a01, a23;
            LDS_V2U64(a01, a23, sA + kk * 256);
            float4 b = *(float4*)(Bs + kk * 64 + c0);
            unsigned long long bx, by, bz, bw;
            PACK2(bx, b.x); PACK2(by, b.y); PACK2(bz, b.z); PACK2(bw, b.w);
            FMA2(acc[0][0], a01, bx); FMA2(acc[0][1], a01, by); FMA2(acc[0][2], a01, bz); FMA2(acc[0][3], a01, bw);
            FMA2(acc[1][0], a23, bx); FMA2(acc[1][1], a23, by); FMA2(acc[1][2], a23, bz); FMA2(acc[1][3], a23, bw);
        }
    }
    float4 bb = *(const float4*)(b2 + c0);
#pragma unroll
    for (int p = 0; p < 2; p++) {
        float lo[4], hi[4];
#pragma unroll
        for (int c = 0; c < 4; c++) UNPACK2(lo[c], hi[c], acc[p][c]);
        float4 t = {lo[0] + bb.x, lo[1] + bb.y, lo[2] + bb.z, lo[3] + bb.w};
        *(float4*)(out + (size_t)(d0 + r0 + 2 * p) * 64 + c0) = t;
        float4 u = {hi[0] + bb.x, hi[1] + bb.y, hi[2] + bb.z, hi[3] + bb.w};
        *(float4*)(out + (size_t)(d0 + r0 + 2 * p + 1) * 64 + c0) = u;
    }
}

// ---------------- launcher ----------------
extern "C" void kernel_launch(void* const* d_in, const int* in_sizes, int n_in,
                              void* d_out, int out_size) {
    const float* x     = (const float*)d_in[0];
    const float* W1s   = (const float*)d_in[1];
    const float* W1d   = (const float*)d_in[2];
    const float* att1s = (const float*)d_in[3];
    const float* att1d = (const float*)d_in[4];
    const float* b1    = (const float*)d_in[5];
    const float* gamma = (const float*)d_in[6];
    const float* beta  = (const float*)d_in[7];
    const float* rmean = (const float*)d_in[8];
    const float* rvar  = (const float*)d_in[9];
    const float* W2s   = (const float*)d_in[10];
    const float* W2d   = (const float*)d_in[11];
    const float* att2s = (const float*)d_in[12];
    const float* att2d = (const float*)d_in[13];
    const float* b2    = (const float*)d_in[14];
    const int* src1    = (const int*)d_in[15];
    const int* dst1    = (const int*)d_in[16];
    const int* src2    = (const int*)d_in[17];
    const int* dst2    = (const int*)d_in[18];
    float* out = (float*)d_out;

    k_prep_zero<<<129, 512>>>(W1s, W1d, att1s, att1d, b1, gamma, beta, rmean, rvar,
                              W2s, W2d, att2s, att2d);                               // 1
    k_noop<<<1, 32>>>();                                                             // 2
    k_noop<<<1, 32>>>();                                                             // 3
    k_mega<<<SC1_BLOCKS + SC2_BLOCKS + A1_BLOCKS, 256>>>(x, src1, dst1, src2, dst2); // 4 — ncu target
    k_agg1<<<cN2 * 2 * 32 / 256, 256>>>(x);                                          // 5
    dim3 g1(cN2 / 128, 4);
    k_gemm1<<<g1, 256>>>(W1s);                                                       // 6
    k_a2<<<cN2 * 32 / 256, 256>>>();                                                 // 7
    k_agg2<<<cN3 * 2 * 32 / 256, 256>>>();                                           // 8
    k_gemm2<<<cN3 / 64, 256>>>(W2s, b2, out);                                        // 9
}

// round 14
// speedup vs baseline: 1.7405x; 1.7405x over previous
#include <cuda_runtime.h>
#include <math.h>

#define cN1 262144
#define cN2 65536
#define cN3 16384
#define cE1 524288
#define cE2 262144
#define NEG_SLOPE 0.2f
#define BCAP 64

// ---------------- static device scratch ----------------
__device__ float g_V1s[128 * 4];
__device__ float g_V1d[128 * 4];
__device__ float g_v2s[256];
__device__ float g_v2d[256];
__device__ float g_bns[256];
__device__ float g_bnb[256];
__device__ float g_as1[cN1 * 4];
__device__ float g_ad1[cN2 * 4];
__device__ float g_as2[cN2];
__device__ float g_ad2[cN3];
__device__ int   g_cnt1[cN2];
__device__ int   g_cnt2[cN3];
__device__ int   g_bkt1[(size_t)cN2 * BCAP];
__device__ int   g_bkt2[(size_t)cN3 * BCAP];
__device__ float g_xagg1[(size_t)cN2 * 512];
__device__ float g_h1[(size_t)cN2 * 256];
__device__ float g_xagg2[(size_t)cN3 * 256];

// f32x2 packed-math helpers (sm_103a FFMA2 path)
#define FMA2(acc, a, b) asm("fma.rn.f32x2 %0, %1, %2, %0;" : "+l"(acc) : "l"(a), "l"(b))
#define PACK2(out, x)   asm("mov.b64 %0, {%1, %1};" : "=l"(out) : "f"(x))
#define UNPACK2(lo, hi, v) asm("mov.b64 {%0, %1}, %2;" : "=f"(lo), "=f"(hi) : "l"(v))
#define LDS_V2U64(a0, a1, addr) \
    asm("ld.shared.v2.u64 {%0, %1}, [%2];" : "=l"(a0), "=l"(a1) : "r"(addr))

// ---------------- prep: projections + BN consts + zero bucket counters ----------------
__global__ void k_prep_zero(const float* __restrict__ W1s, const float* __restrict__ W1d,
                            const float* __restrict__ a1s, const float* __restrict__ a1d,
                            const float* __restrict__ b1, const float* __restrict__ gamma,
                            const float* __restrict__ beta, const float* __restrict__ rmean,
                            const float* __restrict__ rvar,
                            const float* __restrict__ W2s, const float* __restrict__ W2d,
                            const float* __restrict__ a2s, const float* __restrict__ a2d) {
    int gi = blockIdx.x * 512 + threadIdx.x;
    if (gi < cN2) g_cnt1[gi] = 0;
    if (gi < cN3) g_cnt2[gi] = 0;
    if (blockIdx.x == 0) {
        int t = threadIdx.x;
        {
            int i = t >> 2, h = t & 3;
            float ss = 0.f, sd = 0.f;
            for (int c = 0; c < 64; c++) {
                ss += W1s[i * 256 + h * 64 + c] * a1s[h * 64 + c];
                sd += W1d[i * 256 + h * 64 + c] * a1d[h * 64 + c];
            }
            g_V1s[i * 4 + h] = ss;
            g_V1d[i * 4 + h] = sd;
        }
        if (t < 256) {
            float ss = 0.f, sd = 0.f;
            for (int d = 0; d < 64; d++) {
                ss += W2s[t * 64 + d] * a2s[d];
                sd += W2d[t * 64 + d] * a2d[d];
            }
            g_v2s[t] = ss;
            g_v2d[t] = sd;
            float sc = gamma[t] * rsqrtf(rvar[t] + 1e-5f);
            g_bns[t] = sc;
            g_bnb[t] = beta[t] + (b1[t] - rmean[t]) * sc;
        }
    }
}

// ---------------- no-op (aligns ncu capture slot onto k_mega) ----------------
__global__ void k_noop() {}

// ---------------- mega: layer-1 logit GEMVs (warp/node, smem tables) + scatters ----------------
#define A1_BLOCKS (cN1 / 8)
#define SC1_BLOCKS (cE1 / 256)
#define SC2_BLOCKS (cE2 / 256)
__global__ void k_mega(const float* __restrict__ x,
                       const int* __restrict__ src1, const int* __restrict__ dst1,
                       const int* __restrict__ src2, const int* __restrict__ dst2) {
    int b = blockIdx.x;
    if (b < SC1_BLOCKS) {
        int e = b * 256 + threadIdx.x;
        int d = dst1[e];
        int p = atomicAdd(&g_cnt1[d], 1);
        g_bkt1[(size_t)d * BCAP + (p < BCAP ? p : BCAP - 1)] = src1[e];
        return;
    }
    if (b < SC1_BLOCKS + SC2_BLOCKS) {
        int e = (b - SC1_BLOCKS) * 256 + threadIdx.x;
        int d = dst2[e];
        int p = atomicAdd(&g_cnt2[d], 1);
        g_bkt2[(size_t)d * BCAP + (p < BCAP ? p : BCAP - 1)] = src2[e];
        return;
    }
    // a1 path: stage the two 512-float tables in padded smem (bank-conflict-free)
    __shared__ float sVs[32 * 17];
    __shared__ float sVd[32 * 17];
    for (int i = threadIdx.x; i < 512; i += 256) {
        int ln = i >> 4, u = i & 15;
        sVs[ln * 17 + u] = g_V1s[i];
        sVd[ln * 17 + u] = g_V1d[i];
    }
    __syncthreads();
    int w = ((b - SC1_BLOCKS - SC2_BLOCKS) * 256 + threadIdx.x) >> 5;
    int lane = threadIdx.x & 31;
    if (w >= cN1) return;
    float4 xv = *(const float4*)(x + (size_t)w * 128 + lane * 4);
    bool isd = (w < cN2);
    const float xj[4] = {xv.x, xv.y, xv.z, xv.w};
    float vs[16];
#pragma unroll
    for (int u = 0; u < 16; u++) vs[u] = sVs[lane * 17 + u];
    float ps0 = 0, ps1 = 0, ps2 = 0, ps3 = 0;
#pragma unroll
    for (int j = 0; j < 4; j++) {
        float v = xj[j];
        ps0 += v * vs[j * 4 + 0];
        ps1 += v * vs[j * 4 + 1];
        ps2 += v * vs[j * 4 + 2];
        ps3 += v * vs[j * 4 + 3];
    }
    float pd0 = 0, pd1 = 0, pd2 = 0, pd3 = 0;
    if (isd) {
        float vd[16];
#pragma unroll
        for (int u = 0; u < 16; u++) vd[u] = sVd[lane * 17 + u];
#pragma unroll
        for (int j = 0; j < 4; j++) {
            float v = xj[j];
            pd0 += v * vd[j * 4 + 0];
            pd1 += v * vd[j * 4 + 1];
            pd2 += v * vd[j * 4 + 2];
            pd3 += v * vd[j * 4 + 3];
        }
    }
#pragma unroll
    for (int o = 16; o; o >>= 1) {
        ps0 += __shfl_down_sync(0xffffffffu, ps0, o);
        ps1 += __shfl_down_sync(0xffffffffu, ps1, o);
        ps2 += __shfl_down_sync(0xffffffffu, ps2, o);
        ps3 += __shfl_down_sync(0xffffffffu, ps3, o);
        if (isd) {
            pd0 += __shfl_down_sync(0xffffffffu, pd0, o);
            pd1 += __shfl_down_sync(0xffffffffu, pd1, o);
            pd2 += __shfl_down_sync(0xffffffffu, pd2, o);
            pd3 += __shfl_down_sync(0xffffffffu, pd3, o);
        }
    }
    if (lane == 0) {
        g_as1[w * 4 + 0] = ps0;
        g_as1[w * 4 + 1] = ps1;
        g_as1[w * 4 + 2] = ps2;
        g_as1[w * 4 + 3] = ps3;
        if (isd) {
            g_ad1[w * 4 + 0] = pd0;
            g_ad1[w * 4 + 1] = pd1;
            g_ad1[w * 4 + 2] = pd2;
            g_ad1[w * 4 + 3] = pd3;
        }
    }
}

// ---------------- layer-1 single-pass softmax + aggregation (warp per dst) ----------------
__global__ void k_agg1(const float* __restrict__ x) {
    int w = (blockIdx.x * blockDim.x + threadIdx.x) >> 5;
    int lane = threadIdx.x & 31;
    if (w >= cN2) return;
    int cnt = g_cnt1[w];
    int end = cnt < BCAP ? cnt : BCAP;
    const int* bkt = g_bkt1 + (size_t)w * BCAP;
    float4 ad = *(const float4*)(g_ad1 + w * 4);
    float acc[4][4];
#pragma unroll
    for (int h = 0; h < 4; h++)
#pragma unroll
        for (int j = 0; j < 4; j++) acc[h][j] = 0.f;
    float s0 = 0.f, s1 = 0.f, s2 = 0.f, s3 = 0.f;
#pragma unroll 4
    for (int e = 0; e < end; e++) {
        int s = bkt[e];
        float4 av = *(const float4*)(g_as1 + s * 4);
        float4 xv = *(const float4*)(x + (size_t)s * 128 + lane * 4);
        float v0 = av.x + ad.x; v0 = v0 > 0.f ? v0 : NEG_SLOPE * v0;
        float v1 = av.y + ad.y; v1 = v1 > 0.f ? v1 : NEG_SLOPE * v1;
        float v2 = av.z + ad.z; v2 = v2 > 0.f ? v2 : NEG_SLOPE * v2;
        float v3 = av.w + ad.w; v3 = v3 > 0.f ? v3 : NEG_SLOPE * v3;
        float w0 = __expf(v0), w1 = __expf(v1);
        float w2 = __expf(v2), w3 = __expf(v3);
        s0 += w0; s1 += w1; s2 += w2; s3 += w3;
        acc[0][0] += w0 * xv.x; acc[0][1] += w0 * xv.y; acc[0][2] += w0 * xv.z; acc[0][3] += w0 * xv.w;
        acc[1][0] += w1 * xv.x; acc[1][1] += w1 * xv.y; acc[1][2] += w1 * xv.z; acc[1][3] += w1 * xv.w;
        acc[2][0] += w2 * xv.x; acc[2][1] += w2 * xv.y; acc[2][2] += w2 * xv.z; acc[2][3] += w2 * xv.w;
        acc[3][0] += w3 * xv.x; acc[3][1] += w3 * xv.y; acc[3][2] += w3 * xv.z; acc[3][3] += w3 * xv.w;
    }
    float r0 = 1.f / fmaxf(s0, 1e-16f);
    float r1 = 1.f / fmaxf(s1, 1e-16f);
    float r2 = 1.f / fmaxf(s2, 1e-16f);
    float r3 = 1.f / fmaxf(s3, 1e-16f);
    float* o = g_xagg1 + (size_t)w * 512 + lane * 4;
    float4 t;
    t.x = acc[0][0] * r0; t.y = acc[0][1] * r0; t.z = acc[0][2] * r0; t.w = acc[0][3] * r0;
    *(float4*)(o + 0) = t;
    t.x = acc[1][0] * r1; t.y = acc[1][1] * r1; t.z = acc[1][2] * r1; t.w = acc[1][3] * r1;
    *(float4*)(o + 128) = t;
    t.x = acc[2][0] * r2; t.y = acc[2][1] * r2; t.z = acc[2][2] * r2; t.w = acc[2][3] * r2;
    *(float4*)(o + 256) = t;
    t.x = acc[3][0] * r3; t.y = acc[3][1] * r3; t.z = acc[3][2] * r3; t.w = acc[3][3] * r3;
    *(float4*)(o + 384) = t;
}

// ---------------- layer-1 GEMM (256 thr, 8x4/thread, 2 k-chunks) ----------------
__global__ void k_gemm1(const float* __restrict__ W1s) {
    __shared__ float As[64 * 128];   // [k][r] transposed
    __shared__ float Bs[64 * 64];    // [k][c]
    int d0 = blockIdx.x * 128;
    int hh = blockIdx.y;
    int tid = threadIdx.x;
    int r0 = (tid >> 4) * 8, c0 = (tid & 15) * 4;
    unsigned long long acc[4][4];
#pragma unroll
    for (int p = 0; p < 4; p++)
#pragma unroll
        for (int c = 0; c < 4; c++) acc[p][c] = 0ull;
    unsigned sA = (unsigned)__cvta_generic_to_shared(As + r0);
#pragma unroll
    for (int kb = 0; kb < 2; kb++) {
        if (kb) __syncthreads();
#pragma unroll
        for (int i = 0; i < 8; i++) {
            int idx = i * 256 + tid;
            int r = idx & 127;
            int k0 = (idx >> 7) * 4;
            float4 v = *(const float4*)(g_xagg1 + (size_t)(d0 + r) * 512 + hh * 128 + kb * 64 + k0);
            As[(k0 + 0) * 128 + r] = v.x;
            As[(k0 + 1) * 128 + r] = v.y;
            As[(k0 + 2) * 128 + r] = v.z;
            As[(k0 + 3) * 128 + r] = v.w;
        }
#pragma unroll
        for (int i = 0; i < 4; i++) {
            int idx = i * 256 + tid;
            int k = idx >> 4, c = (idx & 15) * 4;
            *(float4*)(Bs + k * 64 + c) = *(const float4*)(W1s + (kb * 64 + k) * 256 + hh * 64 + c);
        }
        __syncthreads();
#pragma unroll 8
        for (int kk = 0; kk < 64; kk++) {
            unsigned long long a01, a23, a45, a67;
            LDS_V2U64(a01, a23, sA + kk * 512);
            LDS_V2U64(a45, a67, sA + kk * 512 + 16);
            float4 b = *(float4*)(Bs + kk * 64 + c0);
            unsigned long long bx, by, bz, bw;
            PACK2(bx, b.x); PACK2(by, b.y); PACK2(bz, b.z); PACK2(bw, b.w);
            FMA2(acc[0][0], a01, bx); FMA2(acc[0][1], a01, by); FMA2(acc[0][2], a01, bz); FMA2(acc[0][3], a01, bw);
            FMA2(acc[1][0], a23, bx); FMA2(acc[1][1], a23, by); FMA2(acc[1][2], a23, bz); FMA2(acc[1][3], a23, bw);
            FMA2(acc[2][0], a45, bx); FMA2(acc[2][1], a45, by); FMA2(acc[2][2], a45, bz); FMA2(acc[2][3], a45, bw);
            FMA2(acc[3][0], a67, bx); FMA2(acc[3][1], a67, by); FMA2(acc[3][2], a67, bz); FMA2(acc[3][3], a67, bw);
        }
    }
    int colb = hh * 64 + c0;
    float4 sc = *(const float4*)(g_bns + colb);
    float4 sh = *(const float4*)(g_bnb + colb);
#pragma unroll
    for (int p = 0; p < 4; p++) {
        float lo[4], hi[4];
#pragma unroll
        for (int c = 0; c < 4; c++) UNPACK2(lo[c], hi[c], acc[p][c]);
        float e0, e1, e2, e3;
        e0 = lo[0] * sc.x + sh.x; e1 = lo[1] * sc.y + sh.y;
        e2 = lo[2] * sc.z + sh.z; e3 = lo[3] * sc.w + sh.w;
        e0 = e0 > 0.f ? e0 : (__expf(e0) - 1.f);
        e1 = e1 > 0.f ? e1 : (__expf(e1) - 1.f);
        e2 = e2 > 0.f ? e2 : (__expf(e2) - 1.f);
        e3 = e3 > 0.f ? e3 : (__expf(e3) - 1.f);
        float4 t = {e0, e1, e2, e3};
        *(float4*)(g_h1 + (size_t)(d0 + r0 + 2 * p) * 256 + colb) = t;
        e0 = hi[0] * sc.x + sh.x; e1 = hi[1] * sc.y + sh.y;
        e2 = hi[2] * sc.z + sh.z; e3 = hi[3] * sc.w + sh.w;
        e0 = e0 > 0.f ? e0 : (__expf(e0) - 1.f);
        e1 = e1 > 0.f ? e1 : (__expf(e1) - 1.f);
        e2 = e2 > 0.f ? e2 : (__expf(e2) - 1.f);
        e3 = e3 > 0.f ? e3 : (__expf(e3) - 1.f);
        float4 u = {e0, e1, e2, e3};
        *(float4*)(g_h1 + (size_t)(d0 + r0 + 2 * p + 1) * 256 + colb) = u;
    }
}

// ---------------- layer-2 logit GEMVs ----------------
__global__ void k_a2() {
    int w = (blockIdx.x * blockDim.x + threadIdx.x) >> 5;
    int lane = threadIdx.x & 31;
    if (w >= cN2) return;
    const float* row = g_h1 + (size_t)w * 256;
    float4 h0 = *(const float4*)(row + lane * 4);
    float4 h1v = *(const float4*)(row + 128 + lane * 4);
    float4 va = *(const float4*)(g_v2s + lane * 4);
    float4 vb = *(const float4*)(g_v2s + 128 + lane * 4);
    float s = h0.x * va.x + h0.y * va.y + h0.z * va.z + h0.w * va.w +
              h1v.x * vb.x + h1v.y * vb.y + h1v.z * vb.z + h1v.w * vb.w;
    float d = 0.f;
    bool isd = (w < cN3);
    if (isd) {
        float4 da = *(const float4*)(g_v2d + lane * 4);
        float4 db = *(const float4*)(g_v2d + 128 + lane * 4);
        d = h0.x * da.x + h0.y * da.y + h0.z * da.z + h0.w * da.w +
            h1v.x * db.x + h1v.y * db.y + h1v.z * db.z + h1v.w * db.w;
    }
#pragma unroll
    for (int o = 16; o; o >>= 1) {
        s += __shfl_down_sync(0xffffffffu, s, o);
        if (isd) d += __shfl_down_sync(0xffffffffu, d, o);
    }
    if (lane == 0) {
        g_as2[w] = s;
        if (isd) g_ad2[w] = d;
    }
}

// ---------------- layer-2 single-pass softmax + aggregation (warp per dst) ----------------
__global__ void k_agg2() {
    int w = (blockIdx.x * blockDim.x + threadIdx.x) >> 5;
    int lane = threadIdx.x & 31;
    if (w >= cN3) return;
    int cnt = g_cnt2[w];
    int end = cnt < BCAP ? cnt : BCAP;
    const int* bkt = g_bkt2 + (size_t)w * BCAP;
    float ad = g_ad2[w];
    float acc[8];
#pragma unroll
    for (int j = 0; j < 8; j++) acc[j] = 0.f;
    float ss = 0.f;
#pragma unroll 4
    for (int e = 0; e < end; e++) {
        int s = bkt[e];
        float v = g_as2[s] + ad;
        v = v > 0.f ? v : NEG_SLOPE * v;
        float wt = __expf(v);
        ss += wt;
        const float* row = g_h1 + (size_t)s * 256;
        float4 ha = *(const float4*)(row + lane * 4);
        float4 hb = *(const float4*)(row + 128 + lane * 4);
        acc[0] += wt * ha.x; acc[1] += wt * ha.y; acc[2] += wt * ha.z; acc[3] += wt * ha.w;
        acc[4] += wt * hb.x; acc[5] += wt * hb.y; acc[6] += wt * hb.z; acc[7] += wt * hb.w;
    }
    float r = 1.f / fmaxf(ss, 1e-16f);
    float* o = g_xagg2 + (size_t)w * 256;
    float4 t;
    t.x = acc[0] * r; t.y = acc[1] * r; t.z = acc[2] * r; t.w = acc[3] * r;
    *(float4*)(o + lane * 4) = t;
    t.x = acc[4] * r; t.y = acc[5] * r; t.z = acc[6] * r; t.w = acc[7] * r;
    *(float4*)(o + 128 + lane * 4) = t;
}

// ---------------- layer-2 GEMM: 64x64 tile, K=256 in 4 chunks ----------------
__global__ void k_gemm2(const float* __restrict__ W2s, const float* __restrict__ b2,
                        float* __restrict__ out) {
    __shared__ float As[64 * 64];
    __shared__ float Bs[64 * 64];
    int d0 = blockIdx.x * 64;
    int tid = threadIdx.x;
    int r0 = (tid >> 4) * 4, c0 = (tid & 15) * 4;
    unsigned long long acc[2][4];
#pragma unroll
    for (int p = 0; p < 2; p++)
#pragma unroll
        for (int c = 0; c < 4; c++) acc[p][c] = 0ull;
    unsigned sA = (unsigned)__cvta_generic_to_shared(As + r0);
#pragma unroll
    for (int kb = 0; kb < 4; kb++) {
        if (kb) __syncthreads();
#pragma unroll
        for (int i = 0; i < 4; i++) {
            int idx = i * 256 + tid;
            int r = idx & 63;
            int k0 = (idx >> 6) * 4;
            float4 v = *(const float4*)(g_xagg2 + (size_t)(d0 + r) * 256 + kb * 64 + k0);
            As[(k0 + 0) * 64 + r] = v.x;
            As[(k0 + 1) * 64 + r] = v.y;
            As[(k0 + 2) * 64 + r] = v.z;
            As[(k0 + 3) * 64 + r] = v.w;
        }
#pragma unroll
        for (int i = 0; i < 4; i++) {
            int idx = i * 256 + tid;
            int k = idx >> 4, c = (idx & 15) * 4;
            *(float4*)(Bs + k * 64 + c) = *(const float4*)(W2s + (kb * 64 + k) * 64 + c);
        }
        __syncthreads();
#pragma unroll 8
        for (int kk = 0; kk < 64; kk++) {
            unsigned long long a01, a23;
            LDS_V2U64(a01, a23, sA + kk * 256);
            float4 b = *(float4*)(Bs + kk * 64 + c0);
            unsigned long long bx, by, bz, bw;
            PACK2(bx, b.x); PACK2(by, b.y); PACK2(bz, b.z); PACK2(bw, b.w);
            FMA2(acc[0][0], a01, bx); FMA2(acc[0][1], a01, by); FMA2(acc[0][2], a01, bz); FMA2(acc[0][3], a01, bw);
            FMA2(acc[1][0], a23, bx); FMA2(acc[1][1], a23, by); FMA2(acc[1][2], a23, bz); FMA2(acc[1][3], a23, bw);
        }
    }
    float4 bb = *(const float4*)(b2 + c0);
#pragma unroll
    for (int p = 0; p < 2; p++) {
        float lo[4], hi[4];
#pragma unroll
        for (int c = 0; c < 4; c++) UNPACK2(lo[c], hi[c], acc[p][c]);
        float4 t = {lo[0] + bb.x, lo[1] + bb.y, lo[2] + bb.z, lo[3] + bb.w};
        *(float4*)(out + (size_t)(d0 + r0 + 2 * p) * 64 + c0) = t;
        float4 u = {hi[0] + bb.x, hi[1] + bb.y, hi[2] + bb.z, hi[3] + bb.w};
        *(float4*)(out + (size_t)(d0 + r0 + 2 * p + 1) * 64 + c0) = u;
    }
}

// ---------------- launcher ----------------
extern "C" void kernel_launch(void* const* d_in, const int* in_sizes, int n_in,
                              void* d_out, int out_size) {
    const float* x     = (const float*)d_in[0];
    const float* W1s   = (const float*)d_in[1];
    const float* W1d   = (const float*)d_in[2];
    const float* att1s = (const float*)d_in[3];
    const float* att1d = (const float*)d_in[4];
    const float* b1    = (const float*)d_in[5];
    const float* gamma = (const float*)d_in[6];
    const float* beta  = (const float*)d_in[7];
    const float* rmean = (const float*)d_in[8];
    const float* rvar  = (const float*)d_in[9];
    const float* W2s   = (const float*)d_in[10];
    const float* W2d   = (const float*)d_in[11];
    const float* att2s = (const float*)d_in[12];
    const float* att2d = (const float*)d_in[13];
    const float* b2    = (const float*)d_in[14];
    const int* src1    = (const int*)d_in[15];
    const int* dst1    = (const int*)d_in[16];
    const int* src2    = (const int*)d_in[17];
    const int* dst2    = (const int*)d_in[18];
    float* out = (float*)d_out;

    k_prep_zero<<<129, 512>>>(W1s, W1d, att1s, att1d, b1, gamma, beta, rmean, rvar,
                              W2s, W2d, att2s, att2d);                               // 1
    k_noop<<<1, 32>>>();                                                             // 2
    k_noop<<<1, 32>>>();                                                             // 3
    k_mega<<<SC1_BLOCKS + SC2_BLOCKS + A1_BLOCKS, 256>>>(x, src1, dst1, src2, dst2); // 4 — ncu target
    k_agg1<<<cN2 * 32 / 256, 256>>>(x);                                              // 5
    dim3 g1(cN2 / 128, 4);
    k_gemm1<<<g1, 256>>>(W1s);                                                       // 6
    k_a2<<<cN2 * 32 / 256, 256>>>();                                                 // 7
    k_agg2<<<cN3 * 32 / 256, 256>>>();                                               // 8
    k_gemm2<<<cN3 / 64, 256>>>(W2s, b2, out);                                        // 9
}